// round 1
// baseline (speedup 1.0000x reference)
#include <cuda_runtime.h>
#include <cuda_bf16.h>
#include <cstdint>

#define B   2
#define S   2048
#define H   16
#define HD  64
#define DIM 1024
#define EPS 1e-5f
#define PAD 65          // smem row stride (64 + 1) to kill bank conflicts
#define TILE_F (64*PAD) // floats per 64x64 padded tile

// ---------------- scratch (device globals; allocation-free rule) -------------
// projected tensors, layout [B*H][S][HD]
__device__ float g_q1[(size_t)B*H*S*HD];
__device__ float g_k1[(size_t)B*H*S*HD];
__device__ float g_q2[(size_t)B*H*S*HD];
__device__ float g_k2[(size_t)B*H*S*HD];
__device__ float g_vp[(size_t)B*H*S*HD];
// normalized attention output, layout [B*S][DIM]
__device__ float g_ao[(size_t)B*S*DIM];

// ---------------- shared helpers ---------------------------------------------
__device__ __forceinline__ void gemm16_from_smem(const float* __restrict__ xa_s,
                                                 const float* __restrict__ wb_s,
                                                 int rg, int cg, float acc[16]) {
    // acc[i*4+j] += sum_d xa_s[(4rg+i)*PAD+d] * wb_s[(4cg+j)*PAD+d]
    #pragma unroll 8
    for (int d = 0; d < 64; d++) {
        float xa[4], wb[4];
        #pragma unroll
        for (int i = 0; i < 4; i++) xa[i] = xa_s[(4*rg+i)*PAD + d];
        #pragma unroll
        for (int j = 0; j < 4; j++) wb[j] = wb_s[(4*cg+j)*PAD + d];
        #pragma unroll
        for (int i = 0; i < 4; i++)
            #pragma unroll
            for (int j = 0; j < 4; j++) acc[i*4+j] += xa[i]*wb[j];
    }
}

// ---------------- kernel 1: per-head projections ------------------------------
// grid (B*H, S/64), 256 threads. y[e] = sum_d x[d] * W[h][e][d]
__global__ void proj_kernel(const float* __restrict__ q, const float* __restrict__ k,
                            const float* __restrict__ v,
                            const float* __restrict__ wq1, const float* __restrict__ wk1,
                            const float* __restrict__ wq2, const float* __restrict__ wk2,
                            const float* __restrict__ wv) {
    extern __shared__ float sm[];
    float* sw = sm;              // 5 weight tiles
    float* sx = sm + 5*TILE_F;   // 3 input tiles (q,k,v head slices)
    const int bh = blockIdx.x, b = bh / H, h = bh % H;
    const int s0 = blockIdx.y * 64;
    const int tid = threadIdx.x;

    const float* wsrc[5] = {wq1, wk1, wq2, wk2, wv};
    #pragma unroll
    for (int w = 0; w < 5; w++) {
        const float* src = wsrc[w] + (size_t)h*HD*HD;
        for (int i = tid; i < 4096; i += 256)
            sw[w*TILE_F + (i>>6)*PAD + (i&63)] = src[i];
    }
    const float* xsrc[3] = {q, k, v};
    #pragma unroll
    for (int w = 0; w < 3; w++) {
        const float* src = xsrc[w];
        for (int i = tid; i < 4096; i += 256) {
            int r = i >> 6, d = i & 63;
            sx[w*TILE_F + r*PAD + d] = src[((size_t)(b*S + s0 + r))*DIM + h*HD + d];
        }
    }
    __syncthreads();

    const int rg = tid >> 4, cg = tid & 15;
    float* dsts[5] = {g_q1, g_k1, g_q2, g_k2, g_vp};
    const int xsel[5] = {0, 1, 0, 1, 2};
    #pragma unroll
    for (int w = 0; w < 5; w++) {
        float acc[16] = {};
        gemm16_from_smem(sx + xsel[w]*TILE_F, sw + w*TILE_F, rg, cg, acc);
        float* dst = dsts[w] + ((size_t)bh*S + s0)*HD;
        #pragma unroll
        for (int i = 0; i < 4; i++)
            #pragma unroll
            for (int j = 0; j < 4; j++)
                dst[(4*rg+i)*HD + 4*cg+j] = acc[i*4+j];
    }
}

// ---------------- kernel 2: dual flash attention + groupnorm ------------------
// grid (B*H, S/64), 256 threads. 64 queries per block, stream 64-key tiles.
__global__ void attn_kernel(const float* __restrict__ gain_p) {
    extern __shared__ float sm[];
    float* sQ1 = sm;
    float* sQ2 = sQ1 + TILE_F;
    float* sK1 = sQ2 + TILE_F;
    float* sK2 = sK1 + TILE_F;
    float* sV  = sK2 + TILE_F;
    float* sP1 = sV  + TILE_F;
    float* sP2 = sP1 + TILE_F;
    float* sM1 = sP2 + TILE_F;  // running max branch 1
    float* sL1 = sM1 + 64;      // running sum branch 1
    float* sM2 = sL1 + 64;
    float* sL2 = sM2 + 64;
    float* sA1 = sL2 + 64;      // per-tile correction factors
    float* sA2 = sA1 + 64;

    const int bh = blockIdx.x;
    const int s0 = blockIdx.y * 64;
    const int tid = threadIdx.x;
    const size_t base = (size_t)bh * S * HD;

    for (int i = tid; i < 4096; i += 256) {
        int r = i >> 6, d = i & 63;
        size_t g = base + (size_t)(s0 + r)*HD + d;
        sQ1[r*PAD+d] = g_q1[g];
        sQ2[r*PAD+d] = g_q2[g];
    }
    if (tid < 64) {
        sM1[tid] = -1e30f; sL1[tid] = 0.f;
        sM2[tid] = -1e30f; sL2[tid] = 0.f;
    }

    const int rg = tid >> 4, cg = tid & 15;
    float acc1[16] = {}, acc2[16] = {};

    for (int kt = 0; kt < S/64; kt++) {
        __syncthreads();   // previous iteration's reads of sK/sV/sP done
        for (int i = tid; i < 4096; i += 256) {
            int r = i >> 6, d = i & 63;
            size_t g = base + (size_t)(kt*64 + r)*HD + d;
            sK1[r*PAD+d] = g_k1[g];
            sK2[r*PAD+d] = g_k2[g];
            sV [r*PAD+d] = g_vp[g];
        }
        __syncthreads();

        // scores (both branches), scaled by 1/sqrt(64)
        {
            float p1[16] = {}, p2[16] = {};
            #pragma unroll 4
            for (int d = 0; d < 64; d++) {
                float qa1[4], qa2[4], kb1[4], kb2[4];
                #pragma unroll
                for (int i = 0; i < 4; i++) { qa1[i] = sQ1[(4*rg+i)*PAD+d]; qa2[i] = sQ2[(4*rg+i)*PAD+d]; }
                #pragma unroll
                for (int j = 0; j < 4; j++) { kb1[j] = sK1[(4*cg+j)*PAD+d]; kb2[j] = sK2[(4*cg+j)*PAD+d]; }
                #pragma unroll
                for (int i = 0; i < 4; i++)
                    #pragma unroll
                    for (int j = 0; j < 4; j++) {
                        p1[i*4+j] += qa1[i]*kb1[j];
                        p2[i*4+j] += qa2[i]*kb2[j];
                    }
            }
            #pragma unroll
            for (int i = 0; i < 4; i++)
                #pragma unroll
                for (int j = 0; j < 4; j++) {
                    sP1[(4*rg+i)*PAD + 4*cg+j] = p1[i*4+j] * 0.125f;
                    sP2[(4*rg+i)*PAD + 4*cg+j] = p2[i*4+j] * 0.125f;
                }
        }
        __syncthreads();

        // online-softmax row stats; threads 0..63 -> branch1 rows, 64..127 -> branch2
        if (tid < 128) {
            float* P = (tid < 64) ? sP1 : sP2;
            float* M = (tid < 64) ? sM1 : sM2;
            float* L = (tid < 64) ? sL1 : sL2;
            float* A = (tid < 64) ? sA1 : sA2;
            const int r = tid & 63;
            float mold = M[r];
            float mx = mold;
            #pragma unroll 8
            for (int t = 0; t < 64; t++) mx = fmaxf(mx, P[r*PAD+t]);
            float alpha = __expf(mold - mx);   // mold=-1e30 -> 0 on first tile
            float sum = 0.f;
            #pragma unroll 8
            for (int t = 0; t < 64; t++) {
                float e = __expf(P[r*PAD+t] - mx);
                P[r*PAD+t] = e;
                sum += e;
            }
            M[r] = mx;
            L[r] = L[r]*alpha + sum;
            A[r] = alpha;
        }
        __syncthreads();

        // rescale accumulators, then acc += P @ V
        #pragma unroll
        for (int i = 0; i < 4; i++) {
            float a1 = sA1[4*rg+i], a2 = sA2[4*rg+i];
            #pragma unroll
            for (int j = 0; j < 4; j++) { acc1[i*4+j] *= a1; acc2[i*4+j] *= a2; }
        }
        #pragma unroll 4
        for (int t = 0; t < 64; t++) {
            float pa1[4], pa2[4], vb[4];
            #pragma unroll
            for (int i = 0; i < 4; i++) { pa1[i] = sP1[(4*rg+i)*PAD+t]; pa2[i] = sP2[(4*rg+i)*PAD+t]; }
            #pragma unroll
            for (int j = 0; j < 4; j++) vb[j] = sV[t*PAD + 4*cg+j];
            #pragma unroll
            for (int i = 0; i < 4; i++)
                #pragma unroll
                for (int j = 0; j < 4; j++) {
                    acc1[i*4+j] += pa1[i]*vb[j];
                    acc2[i*4+j] += pa2[i]*vb[j];
                }
        }
    }
    __syncthreads();

    // combine branches: o = acc1/l1 - gain * acc2/l2  (store into sP1)
    const float gain = *gain_p;
    #pragma unroll
    for (int i = 0; i < 4; i++) {
        int r = 4*rg + i;
        float inv1 = 1.f / sL1[r], inv2 = 1.f / sL2[r];
        #pragma unroll
        for (int j = 0; j < 4; j++)
            sP1[r*PAD + 4*cg+j] = acc1[i*4+j]*inv1 - gain*acc2[i*4+j]*inv2;
    }
    __syncthreads();

    // per-(b,s,h) group norm over 64 dims
    if (tid < 64) {
        const int r = tid;
        float sum = 0.f;
        #pragma unroll 8
        for (int t = 0; t < 64; t++) sum += sP1[r*PAD+t];
        float mean = sum * (1.f/64.f);
        float vs = 0.f;
        #pragma unroll 8
        for (int t = 0; t < 64; t++) { float d = sP1[r*PAD+t] - mean; vs += d*d; }
        sM1[r] = mean;
        sL1[r] = rsqrtf(vs*(1.f/64.f) + EPS);
    }
    __syncthreads();

    const int b = bh / H, h = bh % H;
    for (int i = tid; i < 4096; i += 256) {
        int r = i >> 6, c = i & 63;
        float val = (sP1[r*PAD+c] - sM1[r]) * sL1[r];
        g_ao[((size_t)(b*S + s0 + r))*DIM + h*HD + c] = val;
    }
}

// ---------------- kernel 3: output projection out = ao @ wo^T -----------------
// grid (B*S/64, DIM/64), 256 threads, 64x64 output tile, 4x4 per thread.
__global__ void out_gemm_kernel(const float* __restrict__ wo, float* __restrict__ out) {
    __shared__ float xs[TILE_F];
    __shared__ float ws[TILE_F];
    const int n0 = blockIdx.x * 64;
    const int e0 = blockIdx.y * 64;
    const int tid = threadIdx.x;
    const int rg = tid >> 4, cg = tid & 15;
    float acc[16] = {};
    for (int kt = 0; kt < DIM/64; kt++) {
        __syncthreads();
        for (int i = tid; i < 4096; i += 256) {
            int r = i >> 6, d = i & 63;
            xs[r*PAD+d] = g_ao[(size_t)(n0+r)*DIM + kt*64 + d];
            ws[r*PAD+d] = wo[(size_t)(e0+r)*DIM + kt*64 + d];
        }
        __syncthreads();
        gemm16_from_smem(xs, ws, rg, cg, acc);
    }
    #pragma unroll
    for (int i = 0; i < 4; i++)
        #pragma unroll
        for (int j = 0; j < 4; j++)
            out[(size_t)(n0 + 4*rg+i)*DIM + e0 + 4*cg+j] = acc[i*4+j];
}

// ---------------- launch ------------------------------------------------------
extern "C" void kernel_launch(void* const* d_in, const int* in_sizes, int n_in,
                              void* d_out, int out_size) {
    const float* q    = (const float*)d_in[0];
    const float* k    = (const float*)d_in[1];
    const float* v    = (const float*)d_in[2];
    const float* wq1  = (const float*)d_in[3];
    const float* wk1  = (const float*)d_in[4];
    const float* wq2  = (const float*)d_in[5];
    const float* wk2  = (const float*)d_in[6];
    const float* wv   = (const float*)d_in[7];
    const float* wo   = (const float*)d_in[8];
    const float* gain = (const float*)d_in[9];
    float* out = (float*)d_out;

    const int smem_proj = (int)((8*TILE_F) * sizeof(float));            // ~130 KB
    const int smem_attn = (int)((7*TILE_F + 6*64) * sizeof(float));     // ~115 KB
    cudaFuncSetAttribute(proj_kernel, cudaFuncAttributeMaxDynamicSharedMemorySize, smem_proj);
    cudaFuncSetAttribute(attn_kernel, cudaFuncAttributeMaxDynamicSharedMemorySize, smem_attn);

    dim3 gp(B*H, S/64);
    proj_kernel<<<gp, 256, smem_proj>>>(q, k, v, wq1, wk1, wq2, wk2, wv);

    dim3 ga(B*H, S/64);
    attn_kernel<<<ga, 256, smem_attn>>>(gain);

    dim3 gg(B*S/64, DIM/64);
    out_gemm_kernel<<<gg, 256>>>(wo, out);
}

// round 2
// speedup vs baseline: 5.1998x; 5.1998x over previous
#include <cuda_runtime.h>
#include <cuda_fp16.h>
#include <cstdint>

#define B   2
#define S   2048
#define H   16
#define HD  64
#define DIM 1024
#define EPS 1e-5f
#define PAD 65          // fp32 smem row stride for proj kernel
#define TILE_F (64*PAD)
#define QSTR 72         // half smem row stride for mma tiles (bank = 4g+l, conflict-free)

// ---------------- scratch (device globals; allocation-free rule) -------------
__device__ __align__(16) __half g_q1h[(size_t)B*H*S*HD];
__device__ __align__(16) __half g_k1h[(size_t)B*H*S*HD];
__device__ __align__(16) __half g_q2h[(size_t)B*H*S*HD];
__device__ __align__(16) __half g_k2h[(size_t)B*H*S*HD];
__device__ __align__(16) __half g_vph[(size_t)B*H*S*HD];
__device__ __align__(16) __half g_aoh[(size_t)B*S*DIM];

// ---------------- mma helpers -------------------------------------------------
__device__ __forceinline__ void mma16816(float* d, uint32_t a0, uint32_t a1,
                                         uint32_t a2, uint32_t a3,
                                         uint32_t b0, uint32_t b1) {
    asm volatile(
        "mma.sync.aligned.m16n8k16.row.col.f32.f16.f16.f32 "
        "{%0,%1,%2,%3}, {%4,%5,%6,%7}, {%8,%9}, {%0,%1,%2,%3};\n"
        : "+f"(d[0]), "+f"(d[1]), "+f"(d[2]), "+f"(d[3])
        : "r"(a0), "r"(a1), "r"(a2), "r"(a3), "r"(b0), "r"(b1));
}

__device__ __forceinline__ uint2 ldsm_x2_trans(uint32_t addr) {
    uint2 r;
    asm volatile("ldmatrix.sync.aligned.m8n8.x2.trans.shared.b16 {%0,%1}, [%2];"
                 : "=r"(r.x), "=r"(r.y) : "r"(addr));
    return r;
}

// ---------------- kernel 1: per-head projections (fp32 math, fp16 out) --------
__device__ __forceinline__ void gemm16_from_smem(const float* __restrict__ xa_s,
                                                 const float* __restrict__ wb_s,
                                                 int rg, int cg, float acc[16]) {
    #pragma unroll 8
    for (int d = 0; d < 64; d++) {
        float xa[4], wb[4];
        #pragma unroll
        for (int i = 0; i < 4; i++) xa[i] = xa_s[(4*rg+i)*PAD + d];
        #pragma unroll
        for (int j = 0; j < 4; j++) wb[j] = wb_s[(4*cg+j)*PAD + d];
        #pragma unroll
        for (int i = 0; i < 4; i++)
            #pragma unroll
            for (int j = 0; j < 4; j++) acc[i*4+j] += xa[i]*wb[j];
    }
}

__global__ void proj_kernel(const float* __restrict__ q, const float* __restrict__ k,
                            const float* __restrict__ v,
                            const float* __restrict__ wq1, const float* __restrict__ wk1,
                            const float* __restrict__ wq2, const float* __restrict__ wk2,
                            const float* __restrict__ wv) {
    extern __shared__ float sm[];
    float* sw = sm;
    float* sx = sm + 5*TILE_F;
    const int bh = blockIdx.x, b = bh / H, h = bh % H;
    const int s0 = blockIdx.y * 64;
    const int tid = threadIdx.x;

    const float* wsrc[5] = {wq1, wk1, wq2, wk2, wv};
    #pragma unroll
    for (int w = 0; w < 5; w++) {
        const float* src = wsrc[w] + (size_t)h*HD*HD;
        for (int i = tid; i < 4096; i += 256)
            sw[w*TILE_F + (i>>6)*PAD + (i&63)] = src[i];
    }
    const float* xsrc[3] = {q, k, v};
    #pragma unroll
    for (int w = 0; w < 3; w++) {
        const float* src = xsrc[w];
        for (int i = tid; i < 4096; i += 256) {
            int r = i >> 6, d = i & 63;
            sx[w*TILE_F + r*PAD + d] = src[((size_t)(b*S + s0 + r))*DIM + h*HD + d];
        }
    }
    __syncthreads();

    const int rg = tid >> 4, cg = tid & 15;
    __half* dsts[5] = {g_q1h, g_k1h, g_q2h, g_k2h, g_vph};
    const int xsel[5] = {0, 1, 0, 1, 2};
    #pragma unroll
    for (int w = 0; w < 5; w++) {
        float acc[16] = {};
        gemm16_from_smem(sx + xsel[w]*TILE_F, sw + w*TILE_F, rg, cg, acc);
        __half* dst = dsts[w] + ((size_t)bh*S + s0)*HD;
        #pragma unroll
        for (int i = 0; i < 4; i++)
            #pragma unroll
            for (int j = 0; j < 4; j++)
                dst[(4*rg+i)*HD + 4*cg+j] = __float2half(acc[i*4+j]);
    }
}

// ---------------- kernel 2: dual attention (HMMA) + groupnorm -----------------
// block: 256 thr = 8 warps. 128 queries/block, 64-key tiles. Each warp: 16 rows.
__device__ __forceinline__ void attn_branch(const __half* __restrict__ sQ,
                                            const __half* __restrict__ sK,
                                            uint32_t svu, int warp, int g, int l,
                                            int lrow16, float* o, float& la, float& lb) {
    float s[32];
    #pragma unroll
    for (int i = 0; i < 32; i++) s[i] = 0.f;
    // scores: S(16x64) = Q(16x64) @ K^T
    #pragma unroll
    for (int kc = 0; kc < 4; kc++) {
        uint32_t a0 = *(const uint32_t*)&sQ[(warp*16+g  )*QSTR + kc*16 + 2*l    ];
        uint32_t a1 = *(const uint32_t*)&sQ[(warp*16+g+8)*QSTR + kc*16 + 2*l    ];
        uint32_t a2 = *(const uint32_t*)&sQ[(warp*16+g  )*QSTR + kc*16 + 2*l + 8];
        uint32_t a3 = *(const uint32_t*)&sQ[(warp*16+g+8)*QSTR + kc*16 + 2*l + 8];
        #pragma unroll
        for (int nt = 0; nt < 8; nt++) {
            uint32_t b0 = *(const uint32_t*)&sK[(nt*8+g)*QSTR + kc*16 + 2*l    ];
            uint32_t b1 = *(const uint32_t*)&sK[(nt*8+g)*QSTR + kc*16 + 2*l + 8];
            mma16816(&s[nt*4], a0, a1, a2, a3, b0, b1);
        }
    }
    // exp (no max-subtraction: scaled scores are bounded, fp32 safe), lsum, P fp16
    uint32_t P[16];
    #pragma unroll
    for (int nt = 0; nt < 8; nt++) {
        float e0 = __expf(s[4*nt  ]*0.125f);
        float e1 = __expf(s[4*nt+1]*0.125f);
        float e2 = __expf(s[4*nt+2]*0.125f);
        float e3 = __expf(s[4*nt+3]*0.125f);
        la += e0 + e1;
        lb += e2 + e3;
        __half2 h01 = __floats2half2_rn(e0, e1);
        __half2 h23 = __floats2half2_rn(e2, e3);
        P[2*nt]   = *(uint32_t*)&h01;
        P[2*nt+1] = *(uint32_t*)&h23;
    }
    // o += P(16x64) @ V(64x64); A-frags reuse score layout, B via ldmatrix.trans
    #pragma unroll
    for (int kc = 0; kc < 4; kc++) {
        uint32_t a0 = P[4*kc], a1 = P[4*kc+1], a2 = P[4*kc+2], a3 = P[4*kc+3];
        #pragma unroll
        for (int nt = 0; nt < 8; nt++) {
            uint32_t addr = svu + (uint32_t)(((kc*16 + lrow16)*QSTR + nt*8) * 2);
            uint2 bf = ldsm_x2_trans(addr);
            mma16816(&o[nt*4], a0, a1, a2, a3, bf.x, bf.y);
        }
    }
}

__global__ __launch_bounds__(256, 1) void attn_kernel(const float* __restrict__ gain_p) {
    extern __shared__ __half smh[];
    __half* sQ1 = smh;                 // [128][QSTR]
    __half* sQ2 = sQ1 + 128*QSTR;      // [128][QSTR]
    __half* sK1 = sQ2 + 128*QSTR;      // [64][QSTR]
    __half* sK2 = sK1 + 64*QSTR;
    __half* sV  = sK2 + 64*QSTR;

    const int bh = blockIdx.x;
    const int s0 = blockIdx.y * 128;
    const int tid = threadIdx.x;
    const int warp = tid >> 5, lane = tid & 31;
    const int g = lane >> 2, l = lane & 3;
    const int lrow16 = lane & 15;      // ldmatrix x2 row supplier
    const size_t base = (size_t)bh * S * HD;

    for (int i = tid; i < 128*32; i += 256) {
        int r = i >> 5, c = (i & 31) * 2;
        size_t gi = base + (size_t)(s0 + r)*HD + c;
        *(__half2*)&sQ1[r*QSTR+c] = *(const __half2*)&g_q1h[gi];
        *(__half2*)&sQ2[r*QSTR+c] = *(const __half2*)&g_q2h[gi];
    }

    float o1[32], o2[32];
    #pragma unroll
    for (int i = 0; i < 32; i++) { o1[i] = 0.f; o2[i] = 0.f; }
    float l1a = 0.f, l1b = 0.f, l2a = 0.f, l2b = 0.f;
    const uint32_t svu = (uint32_t)__cvta_generic_to_shared(sV);

    for (int kt = 0; kt < S/64; kt++) {
        __syncthreads();
        for (int i = tid; i < 64*32; i += 256) {
            int r = i >> 5, c = (i & 31) * 2;
            size_t gi = base + (size_t)(kt*64 + r)*HD + c;
            *(__half2*)&sK1[r*QSTR+c] = *(const __half2*)&g_k1h[gi];
            *(__half2*)&sK2[r*QSTR+c] = *(const __half2*)&g_k2h[gi];
            *(__half2*)&sV [r*QSTR+c] = *(const __half2*)&g_vph[gi];
        }
        __syncthreads();
        attn_branch(sQ1, sK1, svu, warp, g, l, lrow16, o1, l1a, l1b);
        attn_branch(sQ2, sK2, svu, warp, g, l, lrow16, o2, l2a, l2b);
    }

    // full row sums across the 4 lanes of each quad
    l1a += __shfl_xor_sync(0xffffffffu, l1a, 1); l1a += __shfl_xor_sync(0xffffffffu, l1a, 2);
    l1b += __shfl_xor_sync(0xffffffffu, l1b, 1); l1b += __shfl_xor_sync(0xffffffffu, l1b, 2);
    l2a += __shfl_xor_sync(0xffffffffu, l2a, 1); l2a += __shfl_xor_sync(0xffffffffu, l2a, 2);
    l2b += __shfl_xor_sync(0xffffffffu, l2b, 1); l2b += __shfl_xor_sync(0xffffffffu, l2b, 2);

    const float gain = *gain_p;
    const float i1a = 1.f/l1a, i1b = 1.f/l1b, i2a = 1.f/l2a, i2b = 1.f/l2b;

    float va[16], vb[16];   // this thread's 16 cols of rows (g) and (g+8)
    #pragma unroll
    for (int nt = 0; nt < 8; nt++) {
        va[2*nt]   = o1[4*nt  ]*i1a - gain*o2[4*nt  ]*i2a;
        va[2*nt+1] = o1[4*nt+1]*i1a - gain*o2[4*nt+1]*i2a;
        vb[2*nt]   = o1[4*nt+2]*i1b - gain*o2[4*nt+2]*i2b;
        vb[2*nt+1] = o1[4*nt+3]*i1b - gain*o2[4*nt+3]*i2b;
    }
    // group norm per row over 64 dims (quad reduce)
    float sa = 0.f, sb = 0.f;
    #pragma unroll
    for (int i = 0; i < 16; i++) { sa += va[i]; sb += vb[i]; }
    sa += __shfl_xor_sync(0xffffffffu, sa, 1); sa += __shfl_xor_sync(0xffffffffu, sa, 2);
    sb += __shfl_xor_sync(0xffffffffu, sb, 1); sb += __shfl_xor_sync(0xffffffffu, sb, 2);
    const float ma = sa * (1.f/64.f), mb = sb * (1.f/64.f);
    float qa = 0.f, qb = 0.f;
    #pragma unroll
    for (int i = 0; i < 16; i++) {
        float da = va[i] - ma; qa += da*da;
        float db = vb[i] - mb; qb += db*db;
    }
    qa += __shfl_xor_sync(0xffffffffu, qa, 1); qa += __shfl_xor_sync(0xffffffffu, qa, 2);
    qb += __shfl_xor_sync(0xffffffffu, qb, 1); qb += __shfl_xor_sync(0xffffffffu, qb, 2);
    const float ra = rsqrtf(qa*(1.f/64.f) + EPS);
    const float rb = rsqrtf(qb*(1.f/64.f) + EPS);

    const int b = bh / H, h = bh % H;
    const size_t rowA = (size_t)(b*S + s0 + warp*16 + g)*DIM + h*HD;
    const size_t rowB = rowA + (size_t)8*DIM;
    #pragma unroll
    for (int nt = 0; nt < 8; nt++) {
        int col = nt*8 + 2*l;
        __half2 ha = __floats2half2_rn((va[2*nt]-ma)*ra, (va[2*nt+1]-ma)*ra);
        __half2 hb = __floats2half2_rn((vb[2*nt]-mb)*rb, (vb[2*nt+1]-mb)*rb);
        *(__half2*)&g_aoh[rowA + col] = ha;
        *(__half2*)&g_aoh[rowB + col] = hb;
    }
}

// ---------------- kernel 3: out = ao @ wo^T (HMMA) ----------------------------
__global__ __launch_bounds__(256, 2) void out_gemm_kernel(const float* __restrict__ wo,
                                                          float* __restrict__ out) {
    __shared__ __half sA[128*QSTR];
    __shared__ __half sW[64*QSTR];
    const int n0 = blockIdx.x * 128;
    const int e0 = blockIdx.y * 64;
    const int tid = threadIdx.x;
    const int warp = tid >> 5, lane = tid & 31;
    const int g = lane >> 2, l = lane & 3;
    float acc[32];
    #pragma unroll
    for (int i = 0; i < 32; i++) acc[i] = 0.f;

    for (int kt = 0; kt < DIM/64; kt++) {
        __syncthreads();
        for (int i = tid; i < 128*32; i += 256) {
            int r = i >> 5, c = (i & 31) * 2;
            *(__half2*)&sA[r*QSTR+c] = *(const __half2*)&g_aoh[(size_t)(n0+r)*DIM + kt*64 + c];
        }
        for (int i = tid; i < 64*32; i += 256) {
            int r = i >> 5, c = (i & 31) * 2;
            float2 f = *(const float2*)&wo[(size_t)(e0+r)*DIM + kt*64 + c];
            *(__half2*)&sW[r*QSTR+c] = __floats2half2_rn(f.x, f.y);
        }
        __syncthreads();
        #pragma unroll
        for (int kc = 0; kc < 4; kc++) {
            uint32_t a0 = *(const uint32_t*)&sA[(warp*16+g  )*QSTR + kc*16 + 2*l    ];
            uint32_t a1 = *(const uint32_t*)&sA[(warp*16+g+8)*QSTR + kc*16 + 2*l    ];
            uint32_t a2 = *(const uint32_t*)&sA[(warp*16+g  )*QSTR + kc*16 + 2*l + 8];
            uint32_t a3 = *(const uint32_t*)&sA[(warp*16+g+8)*QSTR + kc*16 + 2*l + 8];
            #pragma unroll
            for (int nt = 0; nt < 8; nt++) {
                uint32_t b0 = *(const uint32_t*)&sW[(nt*8+g)*QSTR + kc*16 + 2*l    ];
                uint32_t b1 = *(const uint32_t*)&sW[(nt*8+g)*QSTR + kc*16 + 2*l + 8];
                mma16816(&acc[nt*4], a0, a1, a2, a3, b0, b1);
            }
        }
    }
    #pragma unroll
    for (int nt = 0; nt < 8; nt++) {
        float2 r0 = make_float2(acc[4*nt],   acc[4*nt+1]);
        float2 r1 = make_float2(acc[4*nt+2], acc[4*nt+3]);
        *(float2*)&out[(size_t)(n0+warp*16+g  )*DIM + e0 + nt*8 + 2*l] = r0;
        *(float2*)&out[(size_t)(n0+warp*16+g+8)*DIM + e0 + nt*8 + 2*l] = r1;
    }
}

// ---------------- launch ------------------------------------------------------
extern "C" void kernel_launch(void* const* d_in, const int* in_sizes, int n_in,
                              void* d_out, int out_size) {
    const float* q    = (const float*)d_in[0];
    const float* k    = (const float*)d_in[1];
    const float* v    = (const float*)d_in[2];
    const float* wq1  = (const float*)d_in[3];
    const float* wk1  = (const float*)d_in[4];
    const float* wq2  = (const float*)d_in[5];
    const float* wk2  = (const float*)d_in[6];
    const float* wv   = (const float*)d_in[7];
    const float* wo   = (const float*)d_in[8];
    const float* gain = (const float*)d_in[9];
    float* out = (float*)d_out;

    const int smem_proj = (int)((8*TILE_F) * sizeof(float));
    const int smem_attn = (int)((2*128 + 3*64) * QSTR * sizeof(__half)); // 64512 B
    cudaFuncSetAttribute(proj_kernel, cudaFuncAttributeMaxDynamicSharedMemorySize, smem_proj);
    cudaFuncSetAttribute(attn_kernel, cudaFuncAttributeMaxDynamicSharedMemorySize, smem_attn);

    dim3 gp(B*H, S/64);
    proj_kernel<<<gp, 256, smem_proj>>>(q, k, v, wq1, wk1, wq2, wk2, wv);

    dim3 ga(B*H, S/128);
    attn_kernel<<<ga, 256, smem_attn>>>(gain);

    dim3 gg(B*S/128, DIM/64);
    out_gemm_kernel<<<gg, 256>>>(wo, out);
}

// round 4
// speedup vs baseline: 6.7502x; 1.2982x over previous
#include <cuda_runtime.h>
#include <cuda_fp16.h>
#include <cstdint>

#define B   2
#define S   2048
#define H   16
#define HD  64
#define DIM 1024
#define EPS 1e-5f
#define QSTR 72         // half smem row stride (bank = 4g+l, conflict-free)

// ---------------- scratch (device globals; allocation-free rule) -------------
__device__ __align__(16) __half g_q1h[(size_t)B*H*S*HD];
__device__ __align__(16) __half g_k1h[(size_t)B*H*S*HD];
__device__ __align__(16) __half g_q2h[(size_t)B*H*S*HD];
__device__ __align__(16) __half g_k2h[(size_t)B*H*S*HD];
__device__ __align__(16) __half g_vph[(size_t)B*H*S*HD];
__device__ __align__(16) __half g_aoh[(size_t)B*S*DIM];
__device__ __align__(16) __half g_woh[(size_t)DIM*DIM];

// ---------------- asm helpers -------------------------------------------------
__device__ __forceinline__ void mma16816(float* d, uint32_t a0, uint32_t a1,
                                         uint32_t a2, uint32_t a3,
                                         uint32_t b0, uint32_t b1) {
    asm volatile(
        "mma.sync.aligned.m16n8k16.row.col.f32.f16.f16.f32 "
        "{%0,%1,%2,%3}, {%4,%5,%6,%7}, {%8,%9}, {%0,%1,%2,%3};\n"
        : "+f"(d[0]), "+f"(d[1]), "+f"(d[2]), "+f"(d[3])
        : "r"(a0), "r"(a1), "r"(a2), "r"(a3), "r"(b0), "r"(b1));
}

__device__ __forceinline__ uint2 ldsm_x2_trans(uint32_t addr) {
    uint2 r;
    asm volatile("ldmatrix.sync.aligned.m8n8.x2.trans.shared.b16 {%0,%1}, [%2];"
                 : "=r"(r.x), "=r"(r.y) : "r"(addr));
    return r;
}

__device__ __forceinline__ void cp_async16(uint32_t saddr, const void* gptr) {
    asm volatile("cp.async.cg.shared.global [%0], [%1], 16;\n"
                 :: "r"(saddr), "l"(gptr));
}
__device__ __forceinline__ void cp_commit() {
    asm volatile("cp.async.commit_group;\n");
}
template <int N> __device__ __forceinline__ void cp_wait() {
    asm volatile("cp.async.wait_group %0;\n" :: "n"(N));
}

// generic 16-row x 64-col HMMA block: acc[nt*4..] over nt cols of 8
__device__ __forceinline__ void hmma_16x64(const __half* __restrict__ sA,
                                           const __half* __restrict__ sB,
                                           int warp, int g, int l, float* acc) {
    #pragma unroll
    for (int kc = 0; kc < 4; kc++) {
        uint32_t a0 = *(const uint32_t*)&sA[(warp*16+g  )*QSTR + kc*16 + 2*l    ];
        uint32_t a1 = *(const uint32_t*)&sA[(warp*16+g+8)*QSTR + kc*16 + 2*l    ];
        uint32_t a2 = *(const uint32_t*)&sA[(warp*16+g  )*QSTR + kc*16 + 2*l + 8];
        uint32_t a3 = *(const uint32_t*)&sA[(warp*16+g+8)*QSTR + kc*16 + 2*l + 8];
        #pragma unroll
        for (int nt = 0; nt < 8; nt++) {
            uint32_t b0 = *(const uint32_t*)&sB[(nt*8+g)*QSTR + kc*16 + 2*l    ];
            uint32_t b1 = *(const uint32_t*)&sB[(nt*8+g)*QSTR + kc*16 + 2*l + 8];
            mma16816(&acc[nt*4], a0, a1, a2, a3, b0, b1);
        }
    }
}

// ---------------- kernel 0: wo fp32 -> fp16 -----------------------------------
__global__ void convert_wo_kernel(const float* __restrict__ wo) {
    int i = (blockIdx.x * 256 + threadIdx.x) * 2;
    float2 f = *(const float2*)&wo[i];
    *(__half2*)&g_woh[i] = __floats2half2_rn(f.x, f.y);
}

// ---------------- kernel 1: per-head projections (HMMA) -----------------------
// grid (B*H, S/128), 256 threads. y[s][e] = sum_d x[s][d]*W[h][e][d]
__global__ __launch_bounds__(256, 1) void proj_kernel(
        const float* __restrict__ q, const float* __restrict__ k,
        const float* __restrict__ v,
        const float* __restrict__ wq1, const float* __restrict__ wk1,
        const float* __restrict__ wq2, const float* __restrict__ wk2,
        const float* __restrict__ wv) {
    extern __shared__ __half smp[];
    __half* sX = smp;               // 3 x [128][QSTR]
    __half* sW = smp + 3*128*QSTR;  // 5 x [64][QSTR]

    const int bh = blockIdx.x, b = bh / H, h = bh % H;
    const int s0 = blockIdx.y * 128;
    const int tid = threadIdx.x;
    const int warp = tid >> 5, lane = tid & 31;
    const int g = lane >> 2, l = lane & 3;

    const float* xsrc[3] = {q, k, v};
    #pragma unroll
    for (int w = 0; w < 3; w++) {
        for (int i = tid; i < 128*32; i += 256) {
            int r = i >> 5, c = (i & 31) * 2;
            float2 f = *(const float2*)&xsrc[w][((size_t)(b*S + s0 + r))*DIM + h*HD + c];
            *(__half2*)&sX[w*128*QSTR + r*QSTR + c] = __floats2half2_rn(f.x, f.y);
        }
    }
    const float* wsrc[5] = {wq1, wk1, wq2, wk2, wv};
    #pragma unroll
    for (int w = 0; w < 5; w++) {
        const float* src = wsrc[w] + (size_t)h*HD*HD;
        for (int i = tid; i < 64*32; i += 256) {
            int r = i >> 5, c = (i & 31) * 2;
            float2 f = *(const float2*)&src[r*64 + c];
            *(__half2*)&sW[w*64*QSTR + r*QSTR + c] = __floats2half2_rn(f.x, f.y);
        }
    }
    __syncthreads();

    __half* dsts[5] = {g_q1h, g_k1h, g_q2h, g_k2h, g_vph};
    const int xsel[5] = {0, 1, 0, 1, 2};
    #pragma unroll
    for (int w = 0; w < 5; w++) {
        float acc[32];
        #pragma unroll
        for (int i = 0; i < 32; i++) acc[i] = 0.f;
        hmma_16x64(sX + xsel[w]*128*QSTR, sW + w*64*QSTR, warp, g, l, acc);
        __half* dst = dsts[w] + ((size_t)bh*S + s0)*HD;
        #pragma unroll
        for (int nt = 0; nt < 8; nt++) {
            int col = nt*8 + 2*l;
            *(__half2*)&dst[(warp*16+g  )*HD + col] = __floats2half2_rn(acc[4*nt  ], acc[4*nt+1]);
            *(__half2*)&dst[(warp*16+g+8)*HD + col] = __floats2half2_rn(acc[4*nt+2], acc[4*nt+3]);
        }
    }
}

// ---------------- kernel 2: dual attention (HMMA) + groupnorm -----------------
__device__ __forceinline__ void attn_branch(const __half* __restrict__ sQ,
                                            const __half* __restrict__ sK,
                                            uint32_t svu, int warp, int g, int l,
                                            int lrow16, float* o, float& la, float& lb) {
    float s[32];
    #pragma unroll
    for (int i = 0; i < 32; i++) s[i] = 0.f;
    hmma_16x64(sQ, sK, warp, g, l, s);
    uint32_t P[16];
    #pragma unroll
    for (int nt = 0; nt < 8; nt++) {
        float e0 = __expf(s[4*nt  ]*0.125f);
        float e1 = __expf(s[4*nt+1]*0.125f);
        float e2 = __expf(s[4*nt+2]*0.125f);
        float e3 = __expf(s[4*nt+3]*0.125f);
        la += e0 + e1;
        lb += e2 + e3;
        __half2 h01 = __floats2half2_rn(e0, e1);
        __half2 h23 = __floats2half2_rn(e2, e3);
        P[2*nt]   = *(uint32_t*)&h01;
        P[2*nt+1] = *(uint32_t*)&h23;
    }
    #pragma unroll
    for (int kc = 0; kc < 4; kc++) {
        uint32_t a0 = P[4*kc], a1 = P[4*kc+1], a2 = P[4*kc+2], a3 = P[4*kc+3];
        #pragma unroll
        for (int nt = 0; nt < 8; nt++) {
            uint32_t addr = svu + (uint32_t)(((kc*16 + lrow16)*QSTR + nt*8) * 2);
            uint2 bf = ldsm_x2_trans(addr);
            mma16816(&o[nt*4], a0, a1, a2, a3, bf.x, bf.y);
        }
    }
}

#define KV_TILE_H (64*QSTR)   // halves per K/V stage tile

__global__ __launch_bounds__(256, 1) void attn_kernel(const float* __restrict__ gain_p) {
    extern __shared__ __half smh[];
    __half* sQ1 = smh;                  // [128][QSTR]
    __half* sQ2 = sQ1 + 128*QSTR;
    __half* sKV = sQ2 + 128*QSTR;       // 2 stages x {K1,K2,V} x [64][QSTR]

    const int bh = blockIdx.x;
    const int s0 = blockIdx.y * 128;
    const int tid = threadIdx.x;
    const int warp = tid >> 5, lane = tid & 31;
    const int g = lane >> 2, l = lane & 3;
    const int lrow16 = lane & 15;
    const size_t base = (size_t)bh * S * HD;

    for (int i = tid; i < 128*32; i += 256) {
        int r = i >> 5, c = (i & 31) * 2;
        size_t gi = base + (size_t)(s0 + r)*HD + c;
        *(__half2*)&sQ1[r*QSTR+c] = *(const __half2*)&g_q1h[gi];
        *(__half2*)&sQ2[r*QSTR+c] = *(const __half2*)&g_q2h[gi];
    }

    const uint32_t skv_u = (uint32_t)__cvta_generic_to_shared(sKV);
    const __half* gsrc[3] = {g_k1h, g_k2h, g_vph};

    // issue one 64-row tile (3 arrays) into stage st
    auto issue_tile = [&](int kt, int st) {
        #pragma unroll
        for (int a = 0; a < 3; a++) {
            #pragma unroll
            for (int t = 0; t < 2; t++) {
                int chunk = tid + t*256;        // 512 chunks of 16B per array
                int r = chunk >> 3, c8 = (chunk & 7) * 8;
                uint32_t sa = skv_u + (uint32_t)((st*3 + a)*KV_TILE_H + r*QSTR + c8) * 2;
                cp_async16(sa, gsrc[a] + base + (size_t)(kt*64 + r)*HD + c8);
            }
        }
        cp_commit();
    };

    float o1[32], o2[32];
    #pragma unroll
    for (int i = 0; i < 32; i++) { o1[i] = 0.f; o2[i] = 0.f; }
    float l1a = 0.f, l1b = 0.f, l2a = 0.f, l2b = 0.f;

    const int KT = S/64;
    issue_tile(0, 0);
    for (int kt = 0; kt < KT; kt++) {
        const int cur = kt & 1;
        if (kt + 1 < KT) { issue_tile(kt+1, cur ^ 1); cp_wait<1>(); }
        else             { cp_wait<0>(); }
        __syncthreads();
        const __half* sK1 = sKV + (cur*3    )*KV_TILE_H;
        const __half* sK2 = sKV + (cur*3 + 1)*KV_TILE_H;
        const uint32_t svu = skv_u + (uint32_t)((cur*3 + 2)*KV_TILE_H)*2;
        attn_branch(sQ1, sK1, svu, warp, g, l, lrow16, o1, l1a, l1b);
        attn_branch(sQ2, sK2, svu, warp, g, l, lrow16, o2, l2a, l2b);
        __syncthreads();
    }

    l1a += __shfl_xor_sync(0xffffffffu, l1a, 1); l1a += __shfl_xor_sync(0xffffffffu, l1a, 2);
    l1b += __shfl_xor_sync(0xffffffffu, l1b, 1); l1b += __shfl_xor_sync(0xffffffffu, l1b, 2);
    l2a += __shfl_xor_sync(0xffffffffu, l2a, 1); l2a += __shfl_xor_sync(0xffffffffu, l2a, 2);
    l2b += __shfl_xor_sync(0xffffffffu, l2b, 1); l2b += __shfl_xor_sync(0xffffffffu, l2b, 2);

    const float gain = *gain_p;
    const float i1a = 1.f/l1a, i1b = 1.f/l1b, i2a = 1.f/l2a, i2b = 1.f/l2b;

    float va[16], vb[16];
    #pragma unroll
    for (int nt = 0; nt < 8; nt++) {
        va[2*nt]   = o1[4*nt  ]*i1a - gain*o2[4*nt  ]*i2a;
        va[2*nt+1] = o1[4*nt+1]*i1a - gain*o2[4*nt+1]*i2a;
        vb[2*nt]   = o1[4*nt+2]*i1b - gain*o2[4*nt+2]*i2b;
        vb[2*nt+1] = o1[4*nt+3]*i1b - gain*o2[4*nt+3]*i2b;
    }
    float sa = 0.f, sb = 0.f;
    #pragma unroll
    for (int i = 0; i < 16; i++) { sa += va[i]; sb += vb[i]; }
    sa += __shfl_xor_sync(0xffffffffu, sa, 1); sa += __shfl_xor_sync(0xffffffffu, sa, 2);
    sb += __shfl_xor_sync(0xffffffffu, sb, 1); sb += __shfl_xor_sync(0xffffffffu, sb, 2);
    const float ma = sa * (1.f/64.f), mb = sb * (1.f/64.f);
    float qa = 0.f, qb = 0.f;
    #pragma unroll
    for (int i = 0; i < 16; i++) {
        float da = va[i] - ma; qa += da*da;
        float db = vb[i] - mb; qb += db*db;
    }
    qa += __shfl_xor_sync(0xffffffffu, qa, 1); qa += __shfl_xor_sync(0xffffffffu, qa, 2);
    qb += __shfl_xor_sync(0xffffffffu, qb, 1); qb += __shfl_xor_sync(0xffffffffu, qb, 2);
    const float ra = rsqrtf(qa*(1.f/64.f) + EPS);
    const float rb = rsqrtf(qb*(1.f/64.f) + EPS);

    const int b = bh / H, h = bh % H;
    const size_t rowA = (size_t)(b*S + s0 + warp*16 + g)*DIM + h*HD;
    const size_t rowB = rowA + (size_t)8*DIM;
    #pragma unroll
    for (int nt = 0; nt < 8; nt++) {
        int col = nt*8 + 2*l;
        *(__half2*)&g_aoh[rowA + col] = __floats2half2_rn((va[2*nt]-ma)*ra, (va[2*nt+1]-ma)*ra);
        *(__half2*)&g_aoh[rowB + col] = __floats2half2_rn((vb[2*nt]-mb)*rb, (vb[2*nt+1]-mb)*rb);
    }
}

// ---------------- kernel 3: out = ao @ wo^T (HMMA, 128x128 tiles) -------------
__global__ __launch_bounds__(256, 1) void out_gemm_kernel(float* __restrict__ out) {
    extern __shared__ __half smg[];
    __half* sA = smg;               // [128][QSTR]
    __half* sW = smg + 128*QSTR;    // [128][QSTR]
    const int n0 = blockIdx.x * 128;
    const int e0 = blockIdx.y * 128;
    const int tid = threadIdx.x;
    const int warp = tid >> 5, lane = tid & 31;
    const int g = lane >> 2, l = lane & 3;
    float acc[64];
    #pragma unroll
    for (int i = 0; i < 64; i++) acc[i] = 0.f;

    for (int kt = 0; kt < DIM/64; kt++) {
        __syncthreads();
        for (int i = tid; i < 128*32; i += 256) {
            int r = i >> 5, c = (i & 31) * 2;
            *(__half2*)&sA[r*QSTR+c] = *(const __half2*)&g_aoh[(size_t)(n0+r)*DIM + kt*64 + c];
            *(__half2*)&sW[r*QSTR+c] = *(const __half2*)&g_woh[(size_t)(e0+r)*DIM + kt*64 + c];
        }
        __syncthreads();
        #pragma unroll
        for (int kc = 0; kc < 4; kc++) {
            uint32_t a0 = *(const uint32_t*)&sA[(warp*16+g  )*QSTR + kc*16 + 2*l    ];
            uint32_t a1 = *(const uint32_t*)&sA[(warp*16+g+8)*QSTR + kc*16 + 2*l    ];
            uint32_t a2 = *(const uint32_t*)&sA[(warp*16+g  )*QSTR + kc*16 + 2*l + 8];
            uint32_t a3 = *(const uint32_t*)&sA[(warp*16+g+8)*QSTR + kc*16 + 2*l + 8];
            #pragma unroll
            for (int nt = 0; nt < 16; nt++) {
                uint32_t b0 = *(const uint32_t*)&sW[(nt*8+g)*QSTR + kc*16 + 2*l    ];
                uint32_t b1 = *(const uint32_t*)&sW[(nt*8+g)*QSTR + kc*16 + 2*l + 8];
                mma16816(&acc[nt*4], a0, a1, a2, a3, b0, b1);
            }
        }
    }
    #pragma unroll
    for (int nt = 0; nt < 16; nt++) {
        *(float2*)&out[(size_t)(n0+warp*16+g  )*DIM + e0 + nt*8 + 2*l] =
            make_float2(acc[4*nt], acc[4*nt+1]);
        *(float2*)&out[(size_t)(n0+warp*16+g+8)*DIM + e0 + nt*8 + 2*l] =
            make_float2(acc[4*nt+2], acc[4*nt+3]);
    }
}

// ---------------- launch ------------------------------------------------------
extern "C" void kernel_launch(void* const* d_in, const int* in_sizes, int n_in,
                              void* d_out, int out_size) {
    const float* q    = (const float*)d_in[0];
    const float* k    = (const float*)d_in[1];
    const float* v    = (const float*)d_in[2];
    const float* wq1  = (const float*)d_in[3];
    const float* wk1  = (const float*)d_in[4];
    const float* wq2  = (const float*)d_in[5];
    const float* wk2  = (const float*)d_in[6];
    const float* wv   = (const float*)d_in[7];
    const float* wo   = (const float*)d_in[8];
    const float* gain = (const float*)d_in[9];
    float* out = (float*)d_out;

    const int smem_proj = (int)((3*128 + 5*64) * QSTR * sizeof(__half));       // 101376
    const int smem_attn = (int)((2*128*QSTR + 6*KV_TILE_H) * sizeof(__half));  // 92160
    const int smem_gemm = (int)((2*128*QSTR) * sizeof(__half));                // 36864
    static bool attr_done = false;
    if (!attr_done) {
        cudaFuncSetAttribute(proj_kernel, cudaFuncAttributeMaxDynamicSharedMemorySize, smem_proj);
        cudaFuncSetAttribute(attn_kernel, cudaFuncAttributeMaxDynamicSharedMemorySize, smem_attn);
        cudaFuncSetAttribute(out_gemm_kernel, cudaFuncAttributeMaxDynamicSharedMemorySize, smem_gemm);
        attr_done = true;
    }

    convert_wo_kernel<<<DIM*DIM/512, 256>>>(wo);

    dim3 gp(B*H, S/128);
    proj_kernel<<<gp, 256, smem_proj>>>(q, k, v, wq1, wk1, wq2, wk2, wv);

    dim3 ga(B*H, S/128);
    attn_kernel<<<ga, 256, smem_attn>>>(gain);

    dim3 gg(B*S/128, DIM/128);
    out_gemm_kernel<<<gg, 256, smem_gemm>>>(out);
}